// round 7
// baseline (speedup 1.0000x reference)
#include <cuda_runtime.h>
#include <math.h>

#define DIMS 20
#define MULT 8
#define KCOMP 168
#define NPAIR (DIMS/2)
#define FROW 24              // fast row: g[20] | 0 | c | pad2   (96B, 16B-aligned)
#define GROW 48              // general row: a[20] | b[20] | c | pad (192B)
#define LOG_NORM (-18.378770664093453f)
#define LN2F 0.6931471805599453f
#define EPS_VAR 1.0f
#define BASE_COV 0.1f
#define LOG2E 1.4426950408889634f

typedef unsigned long long u64;

// global staging written by prep kernel
__device__ float g_fast[4096];          // 168*24 rows + ainv[20] at 4032
__device__ float g_gen[KCOMP * GROW];   // fallback layout
__device__ int   g_flag;

__device__ __forceinline__ u64 pack2f(float lo, float hi) {
    u64 r; asm("mov.b64 %0, {%1, %2};" : "=l"(r) : "f"(lo), "f"(hi)); return r;
}
__device__ __forceinline__ void unpack2f(u64 v, float& lo, float& hi) {
    asm("mov.b64 {%0, %1}, %2;" : "=f"(lo), "=f"(hi) : "l"(v));
}
__device__ __forceinline__ u64 ffma2(u64 a, u64 b, u64 c) {
    u64 d; asm("fma.rn.f32x2 %0, %1, %2, %3;" : "=l"(d) : "l"(a), "l"(b), "l"(c)); return d;
}
__device__ __forceinline__ u64 fmul2(u64 a, u64 b) {
    u64 d; asm("mul.rn.f32x2 %0, %1, %2;" : "=l"(d) : "l"(a), "l"(b)); return d;
}
__device__ __forceinline__ float ex2f(float x) {
    float r; asm("ex2.approx.ftz.f32 %0, %1;" : "=f"(r) : "f"(x)); return r;
}

// ---------------------------------------------------------------------------
// Prep kernel (1 block): softmax, fold constants, emit both layouts + flag.
// Fast layout per k (24 floats): [ g_0..g_19, 0.0, c_k, 0, 0 ]
// ainv pairs at g_fast[4032..4051]: a_d = -0.5*LOG2E*inv0[d]
// ---------------------------------------------------------------------------
__global__ void gm_prep_kernel(const float* __restrict__ alpha,
                               const float* __restrict__ mu,
                               const float* __restrict__ cov) {
    __shared__ float red[256];
    __shared__ int sflag;
    const int t = threadIdx.x;
    if (t == 0) sflag = 1;

    float av = (t < KCOMP) ? alpha[t] : -1e30f;
    red[t] = av; __syncthreads();
    for (int s = 128; s > 0; s >>= 1) { if (t < s) red[t] = fmaxf(red[t], red[t + s]); __syncthreads(); }
    const float mx = red[0]; __syncthreads();
    float ev = (t < KCOMP) ? expf(av - mx) : 0.f;
    red[t] = ev; __syncthreads();
    for (int s = 128; s > 0; s >>= 1) { if (t < s) red[t] += red[t + s]; __syncthreads(); }
    const float w = ev / red[0];

    if (t < KCOMP) {
        const int i = t / MULT;
        float sum_mu2inv = 0.f;
        int ok = 1;
        #pragma unroll
        for (int d = 0; d < DIMS; d++) {
            float sc = (d < i) ? EPS_VAR : 1.0f;
            float inv = 1.0f / (cov[t * DIMS + d] * sc);
            float inv0 = 1.0f / cov[d];
            ok &= (inv == inv0);
            float mm = mu[t * DIMS + d];
            g_fast[t * FROW + d]       = LOG2E * inv * mm;
            g_gen[t * GROW + d]        = -0.5f * LOG2E * inv;
            g_gen[t * GROW + DIMS + d] =  LOG2E * inv * mm;
            sum_mu2inv += mm * mm * inv;
        }
        float log2det = (float)i * log2f(EPS_VAR) + (float)(DIMS - i) * log2f(BASE_COV);
        float c = log2f(w) - 0.5f * log2det - 0.5f * LOG2E * sum_mu2inv;
        g_fast[t * FROW + 20] = 0.f;
        g_fast[t * FROW + 21] = c;
        g_fast[t * FROW + 22] = 0.f;
        g_fast[t * FROW + 23] = 0.f;
        g_gen[t * GROW + 2 * DIMS] = c + LOG2E * LOG_NORM;
        #pragma unroll
        for (int f = 2 * DIMS + 1; f < GROW; f++) g_gen[t * GROW + f] = 0.f;
        if (!ok) atomicAnd(&sflag, 0);
        if (t < DIMS) g_fast[KCOMP * FROW + t] = -0.5f * LOG2E * (1.0f / cov[t]);
    }
    __syncthreads();
    if (t == 0) {
        for (int f = KCOMP * FROW + DIMS; f < 4096; f++) g_fast[f] = 0.f;
        g_flag = sflag;
    }
}

// ---------------------------------------------------------------------------
// Main kernel: flat launch, 128 threads/block, 2 samples/thread (chunk=256).
// Fast path: single 10-FFMA2 chain per (n,k); A_n factored out of the k-loop.
// Row loads via ulonglong2 (LDS.128) -> 6 shared wavefronts per k, not 11.
// ---------------------------------------------------------------------------
__global__ void __launch_bounds__(128, 5)
gm_main_kernel(const float* __restrict__ sample, float* __restrict__ out, int n_total) {
    __shared__ float sB[8192];           // 32KB; fast path uses first 4096
    const int tid = threadIdx.x;
    const int flag = g_flag;

    if (flag) {
        const float4* src = (const float4*)g_fast;
        float4* dst = (float4*)sB;
        #pragma unroll
        for (int it = 0; it < 8; it++) dst[tid + 128 * it] = src[tid + 128 * it];
    } else {
        const float4* src = (const float4*)g_gen;
        float4* dst = (float4*)sB;
        for (int idx = tid; idx < KCOMP * GROW / 4; idx += 128) dst[idx] = src[idx];
    }
    __syncthreads();

    const int base = blockIdx.x * 256;
    int n0 = base + tid;
    int n1 = base + 128 + tid;
    const bool v0 = (n0 < n_total), v1 = (n1 < n_total);
    const size_t i0 = v0 ? (size_t)n0 : 0;
    const size_t i1 = v1 ? (size_t)n1 : 0;

    // sample rows: 80B = 5x16B -> ulonglong2 loads give f32x2 pairs directly
    u64 x0[NPAIR], x1[NPAIR];
    {
        const ulonglong2* p0 = (const ulonglong2*)(sample + i0 * DIMS);
        const ulonglong2* p1 = (const ulonglong2*)(sample + i1 * DIMS);
        #pragma unroll
        for (int j = 0; j < 5; j++) {
            ulonglong2 q0 = p0[j], q1 = p1[j];
            x0[2 * j] = q0.x; x0[2 * j + 1] = q0.y;
            x1[2 * j] = q1.x; x1[2 * j + 1] = q1.y;
        }
    }

    float dens0 = 0.f, dens1 = 0.f;

    if (flag) {
        // ---- A_n = sum_d a_d * x_d^2 (factored out of k-loop)
        u64 aA0, aA1;
        {
            const ulonglong2* ap2 = (const ulonglong2*)(sB + KCOMP * FROW);
            ulonglong2 a01 = ap2[0];
            aA0 = fmul2(fmul2(x0[0], x0[0]), a01.x);
            aA1 = fmul2(fmul2(x1[0], x1[0]), a01.x);
            aA0 = ffma2(fmul2(x0[1], x0[1]), a01.y, aA0);
            aA1 = ffma2(fmul2(x1[1], x1[1]), a01.y, aA1);
            #pragma unroll
            for (int j = 1; j < 5; j++) {
                ulonglong2 aj = ap2[j];
                aA0 = ffma2(fmul2(x0[2 * j], x0[2 * j]), aj.x, aA0);
                aA1 = ffma2(fmul2(x1[2 * j], x1[2 * j]), aj.x, aA1);
                aA0 = ffma2(fmul2(x0[2 * j + 1], x0[2 * j + 1]), aj.y, aA0);
                aA1 = ffma2(fmul2(x1[2 * j + 1], x1[2 * j + 1]), aj.y, aA1);
            }
        }
        float al, ah, A0, A1;
        unpack2f(aA0, al, ah); A0 = al + ah;
        unpack2f(aA1, al, ah); A1 = al + ah;

        #pragma unroll 2
        for (int k = 0; k < KCOMP; k++) {
            // 5x LDS.128 + 1x LDS.64 per row (row base 96B-aligned -> 16B ok)
            const ulonglong2* R2 = (const ulonglong2*)(sB + k * FROW);
            const u64 ck2 = *(const u64*)(sB + k * FROW + 20);   // (0, c)
            ulonglong2 g01 = R2[0], g23 = R2[1], g45 = R2[2], g67 = R2[3], g89 = R2[4];

            u64 acc0 = ffma2(x0[0], g01.x, ck2);
            u64 acc1 = ffma2(x1[0], g01.x, ck2);
            acc0 = ffma2(x0[1], g01.y, acc0);  acc1 = ffma2(x1[1], g01.y, acc1);
            acc0 = ffma2(x0[2], g23.x, acc0);  acc1 = ffma2(x1[2], g23.x, acc1);
            acc0 = ffma2(x0[3], g23.y, acc0);  acc1 = ffma2(x1[3], g23.y, acc1);
            acc0 = ffma2(x0[4], g45.x, acc0);  acc1 = ffma2(x1[4], g45.x, acc1);
            acc0 = ffma2(x0[5], g45.y, acc0);  acc1 = ffma2(x1[5], g45.y, acc1);
            acc0 = ffma2(x0[6], g67.x, acc0);  acc1 = ffma2(x1[6], g67.x, acc1);
            acc0 = ffma2(x0[7], g67.y, acc0);  acc1 = ffma2(x1[7], g67.y, acc1);
            acc0 = ffma2(x0[8], g89.x, acc0);  acc1 = ffma2(x1[8], g89.x, acc1);
            acc0 = ffma2(x0[9], g89.y, acc0);  acc1 = ffma2(x1[9], g89.y, acc1);

            float l, h;
            unpack2f(acc0, l, h); dens0 += ex2f(l + h);
            unpack2f(acc1, l, h); dens1 += ex2f(l + h);
        }

        if (v0) out[n0] = fmaf(A0, LN2F, logf(dens0)) + LOG_NORM;
        if (v1) out[n1] = fmaf(A1, LN2F, logf(dens1)) + LOG_NORM;
    } else {
        // ---- general path: full Horner quadratic (c includes LOG2E*LOG_NORM)
        for (int k = 0; k < KCOMP; k++) {
            const ulonglong2* RA = (const ulonglong2*)(sB + k * GROW);          // a pairs
            const ulonglong2* RB = (const ulonglong2*)(sB + k * GROW + DIMS);   // b pairs
            const u64 c2 = *(const u64*)(sB + k * GROW + 2 * DIMS);
            u64 acc0 = c2, acc1 = c2;
            #pragma unroll
            for (int j = 0; j < 5; j++) {
                ulonglong2 qa = RA[j], qb = RB[j];
                u64 t0 = ffma2(x0[2 * j], qa.x, qb.x);
                acc0 = ffma2(x0[2 * j], t0, acc0);
                u64 t1 = ffma2(x1[2 * j], qa.x, qb.x);
                acc1 = ffma2(x1[2 * j], t1, acc1);
                t0 = ffma2(x0[2 * j + 1], qa.y, qb.y);
                acc0 = ffma2(x0[2 * j + 1], t0, acc0);
                t1 = ffma2(x1[2 * j + 1], qa.y, qb.y);
                acc1 = ffma2(x1[2 * j + 1], t1, acc1);
            }
            float l, h;
            unpack2f(acc0, l, h); dens0 += ex2f(l + h);
            unpack2f(acc1, l, h); dens1 += ex2f(l + h);
        }
        if (v0) out[n0] = logf(dens0);
        if (v1) out[n1] = logf(dens1);
    }
}

extern "C" void kernel_launch(void* const* d_in, const int* in_sizes, int n_in,
                              void* d_out, int out_size) {
    const float* sample = (const float*)d_in[0];
    const float* alpha  = (const float*)d_in[1];
    const float* mu     = (const float*)d_in[2];
    const float* cov    = (const float*)d_in[3];
    float* out = (float*)d_out;

    const int n_total = in_sizes[0] / DIMS;
    const int blocks = (n_total + 255) / 256;     // 2048 for N=524288

    gm_prep_kernel<<<1, 256>>>(alpha, mu, cov);
    gm_main_kernel<<<blocks, 128>>>(sample, out, n_total);
}

// round 9
// speedup vs baseline: 1.1397x; 1.1397x over previous
#include <cuda_runtime.h>
#include <math.h>

#define DIMS 20
#define MULT 8
#define KCOMP 168
#define NPAIR (DIMS/2)
#define FROW 24              // fast row: g[20] | 0 | c | pad2   (96B)
#define GROW 48              // general row: a[20] | b[20] | c | pad
#define LOG_NORM (-18.378770664093453f)
#define LN2F 0.6931471805599453f
#define EPS_VAR 1.0f
#define BASE_COV 0.1f
#define LOG2E 1.4426950408889634f
#define SPT 3
#define CHUNK (128 * SPT)    // samples per block

typedef unsigned long long u64;

// global staging written by prep kernel
__device__ float g_fast[4096];          // 168*24 rows + ainv[20] at 4032
__device__ float g_gen[KCOMP * GROW];   // fallback layout
__device__ int   g_flag;

__device__ __forceinline__ u64 pack2f(float lo, float hi) {
    u64 r; asm("mov.b64 %0, {%1, %2};" : "=l"(r) : "f"(lo), "f"(hi)); return r;
}
__device__ __forceinline__ void unpack2f(u64 v, float& lo, float& hi) {
    asm("mov.b64 {%0, %1}, %2;" : "=f"(lo), "=f"(hi) : "l"(v));
}
__device__ __forceinline__ u64 ffma2(u64 a, u64 b, u64 c) {
    u64 d; asm("fma.rn.f32x2 %0, %1, %2, %3;" : "=l"(d) : "l"(a), "l"(b), "l"(c)); return d;
}
__device__ __forceinline__ u64 fmul2(u64 a, u64 b) {
    u64 d; asm("mul.rn.f32x2 %0, %1, %2;" : "=l"(d) : "l"(a), "l"(b)); return d;
}
__device__ __forceinline__ float ex2f(float x) {
    float r; asm("ex2.approx.ftz.f32 %0, %1;" : "=f"(r) : "f"(x)); return r;
}

// ---------------------------------------------------------------------------
// Prep kernel (1 block): softmax, fold constants, emit both layouts + flag.
// ---------------------------------------------------------------------------
__global__ void gm_prep_kernel(const float* __restrict__ alpha,
                               const float* __restrict__ mu,
                               const float* __restrict__ cov) {
    __shared__ float red[256];
    __shared__ int sflag;
    const int t = threadIdx.x;
    if (t == 0) sflag = 1;

    float av = (t < KCOMP) ? alpha[t] : -1e30f;
    red[t] = av; __syncthreads();
    for (int s = 128; s > 0; s >>= 1) { if (t < s) red[t] = fmaxf(red[t], red[t + s]); __syncthreads(); }
    const float mx = red[0]; __syncthreads();
    float ev = (t < KCOMP) ? expf(av - mx) : 0.f;
    red[t] = ev; __syncthreads();
    for (int s = 128; s > 0; s >>= 1) { if (t < s) red[t] += red[t + s]; __syncthreads(); }
    const float w = ev / red[0];

    if (t < KCOMP) {
        const int i = t / MULT;
        float sum_mu2inv = 0.f;
        int ok = 1;
        #pragma unroll
        for (int d = 0; d < DIMS; d++) {
            float sc = (d < i) ? EPS_VAR : 1.0f;
            float inv = 1.0f / (cov[t * DIMS + d] * sc);
            float inv0 = 1.0f / cov[d];
            ok &= (inv == inv0);
            float mm = mu[t * DIMS + d];
            g_fast[t * FROW + d]       = LOG2E * inv * mm;
            g_gen[t * GROW + d]        = -0.5f * LOG2E * inv;
            g_gen[t * GROW + DIMS + d] =  LOG2E * inv * mm;
            sum_mu2inv += mm * mm * inv;
        }
        float log2det = (float)i * log2f(EPS_VAR) + (float)(DIMS - i) * log2f(BASE_COV);
        float c = log2f(w) - 0.5f * log2det - 0.5f * LOG2E * sum_mu2inv;
        g_fast[t * FROW + 20] = 0.f;
        g_fast[t * FROW + 21] = c;
        g_fast[t * FROW + 22] = 0.f;
        g_fast[t * FROW + 23] = 0.f;
        g_gen[t * GROW + 2 * DIMS] = c + LOG2E * LOG_NORM;
        #pragma unroll
        for (int f = 2 * DIMS + 1; f < GROW; f++) g_gen[t * GROW + f] = 0.f;
        if (!ok) atomicAnd(&sflag, 0);
        if (t < DIMS) g_fast[KCOMP * FROW + t] = -0.5f * LOG2E * (1.0f / cov[t]);
    }
    __syncthreads();
    if (t == 0) {
        for (int f = KCOMP * FROW + DIMS; f < 4096; f++) g_fast[f] = 0.f;
        g_flag = sflag;
    }
}

// ---------------------------------------------------------------------------
// Main kernel: flat launch, 128 threads/block, 3 samples/thread (chunk=384).
// Fast path: 10-FFMA2 chain per (n,k), 3 independent chains per thread;
// g-row loaded as scalar u64 LDS (broadcast, 1 wavefront each), reused 3x.
// ---------------------------------------------------------------------------
__global__ void __launch_bounds__(128, 4)
gm_main_kernel(const float* __restrict__ sample, float* __restrict__ out, int n_total) {
    __shared__ float sB[8192];           // 32KB; fast path uses first 4096
    const int tid = threadIdx.x;
    const int flag = g_flag;

    if (flag) {
        const float4* src = (const float4*)g_fast;
        float4* dst = (float4*)sB;
        #pragma unroll
        for (int it = 0; it < 8; it++) dst[tid + 128 * it] = src[tid + 128 * it];
    } else {
        const float4* src = (const float4*)g_gen;
        float4* dst = (float4*)sB;
        for (int idx = tid; idx < KCOMP * GROW / 4; idx += 128) dst[idx] = src[idx];
    }
    __syncthreads();

    const int base = blockIdx.x * CHUNK;
    const int n0 = base + tid, n1 = base + 128 + tid, n2 = base + 256 + tid;
    const bool v0 = (n0 < n_total), v1 = (n1 < n_total), v2 = (n2 < n_total);
    const size_t i0 = v0 ? (size_t)n0 : 0;
    const size_t i1 = v1 ? (size_t)n1 : 0;
    const size_t i2 = v2 ? (size_t)n2 : 0;

    // sample rows: 80B = 5x16B -> ulonglong2 gmem loads give f32x2 pairs directly
    u64 x0[NPAIR], x1[NPAIR], x2[NPAIR];
    {
        const ulonglong2* p0 = (const ulonglong2*)(sample + i0 * DIMS);
        const ulonglong2* p1 = (const ulonglong2*)(sample + i1 * DIMS);
        const ulonglong2* p2 = (const ulonglong2*)(sample + i2 * DIMS);
        #pragma unroll
        for (int j = 0; j < 5; j++) {
            ulonglong2 q0 = p0[j], q1 = p1[j], q2 = p2[j];
            x0[2 * j] = q0.x; x0[2 * j + 1] = q0.y;
            x1[2 * j] = q1.x; x1[2 * j + 1] = q1.y;
            x2[2 * j] = q2.x; x2[2 * j + 1] = q2.y;
        }
    }

    float dens0 = 0.f, dens1 = 0.f, dens2 = 0.f;

    if (flag) {
        // ---- A_n = sum_d a_d * x_d^2 (factored out of k-loop)
        const u64* ap = (const u64*)(sB + KCOMP * FROW);
        u64 aA0 = fmul2(fmul2(x0[0], x0[0]), ap[0]);
        u64 aA1 = fmul2(fmul2(x1[0], x1[0]), ap[0]);
        u64 aA2 = fmul2(fmul2(x2[0], x2[0]), ap[0]);
        #pragma unroll
        for (int j = 1; j < NPAIR; j++) {
            aA0 = ffma2(fmul2(x0[j], x0[j]), ap[j], aA0);
            aA1 = ffma2(fmul2(x1[j], x1[j]), ap[j], aA1);
            aA2 = ffma2(fmul2(x2[j], x2[j]), ap[j], aA2);
        }
        float al, ah, A0, A1, A2v;
        unpack2f(aA0, al, ah); A0  = al + ah;
        unpack2f(aA1, al, ah); A1  = al + ah;
        unpack2f(aA2, al, ah); A2v = al + ah;

        #pragma unroll 2
        for (int k = 0; k < KCOMP; k++) {
            const u64* R = (const u64*)(sB + k * FROW);   // g pairs [0..9], (0,c) at [10]
            const u64 ck2 = R[10];
            u64 acc0 = ffma2(x0[0], R[0], ck2);
            u64 acc1 = ffma2(x1[0], R[0], ck2);
            u64 acc2 = ffma2(x2[0], R[0], ck2);
            #pragma unroll
            for (int j = 1; j < NPAIR; j++) {
                acc0 = ffma2(x0[j], R[j], acc0);
                acc1 = ffma2(x1[j], R[j], acc1);
                acc2 = ffma2(x2[j], R[j], acc2);
            }
            float l, h;
            unpack2f(acc0, l, h); dens0 += ex2f(l + h);
            unpack2f(acc1, l, h); dens1 += ex2f(l + h);
            unpack2f(acc2, l, h); dens2 += ex2f(l + h);
        }

        if (v0) out[n0] = fmaf(A0,  LN2F, logf(dens0)) + LOG_NORM;
        if (v1) out[n1] = fmaf(A1,  LN2F, logf(dens1)) + LOG_NORM;
        if (v2) out[n2] = fmaf(A2v, LN2F, logf(dens2)) + LOG_NORM;
    } else {
        // ---- general path: full Horner quadratic (c includes LOG2E*LOG_NORM)
        for (int k = 0; k < KCOMP; k++) {
            const u64* R = (const u64*)(sB + k * GROW);   // a[0..9], b[10..19], (c,0)[20]
            const u64 c2 = R[20];
            u64 acc0 = c2, acc1 = c2, acc2 = c2;
            #pragma unroll
            for (int j = 0; j < NPAIR; j++) {
                u64 t0 = ffma2(x0[j], R[j], R[10 + j]);
                acc0 = ffma2(x0[j], t0, acc0);
                u64 t1 = ffma2(x1[j], R[j], R[10 + j]);
                acc1 = ffma2(x1[j], t1, acc1);
                u64 t2 = ffma2(x2[j], R[j], R[10 + j]);
                acc2 = ffma2(x2[j], t2, acc2);
            }
            float l, h;
            unpack2f(acc0, l, h); dens0 += ex2f(l + h);
            unpack2f(acc1, l, h); dens1 += ex2f(l + h);
            unpack2f(acc2, l, h); dens2 += ex2f(l + h);
        }
        if (v0) out[n0] = logf(dens0);
        if (v1) out[n1] = logf(dens1);
        if (v2) out[n2] = logf(dens2);
    }
}

extern "C" void kernel_launch(void* const* d_in, const int* in_sizes, int n_in,
                              void* d_out, int out_size) {
    const float* sample = (const float*)d_in[0];
    const float* alpha  = (const float*)d_in[1];
    const float* mu     = (const float*)d_in[2];
    const float* cov    = (const float*)d_in[3];
    float* out = (float*)d_out;

    const int n_total = in_sizes[0] / DIMS;
    const int blocks = (n_total + CHUNK - 1) / CHUNK;   // 1366 for N=524288

    gm_prep_kernel<<<1, 256>>>(alpha, mu, cov);
    gm_main_kernel<<<blocks, 128>>>(sample, out, n_total);
}

// round 10
// speedup vs baseline: 1.1499x; 1.0089x over previous
#include <cuda_runtime.h>
#include <math.h>

#define DIMS 20
#define MULT 8
#define KCOMP 168
#define NPAIR (DIMS/2)
#define FROW 24              // fast row: g[20] | 0 | c | pad2   (96B)
#define GROW 48              // general row: a[20] | b[20] | c | pad
#define LOG_NORM (-18.378770664093453f)
#define LN2F 0.6931471805599453f
#define EPS_VAR 1.0f
#define BASE_COV 0.1f
#define LOG2E 1.4426950408889634f
#define LOG2_EPSVAR 0.0f                    // log2(EPS_VAR) with EPS=1
#define LOG2_BASECOV (-3.3219280948873623f) // log2(0.1)
#define SPT 3
#define CHUNK (128 * SPT)

// dynamic shared layout (floats):
//   fast path: rows [0, 4032), a-row [4032, 4052), A-stash [4096, 4480)
//   gen  path: rows [0, 8064)
#define DS_FLOATS 8448       // 33792 bytes
#define DS_AROW   4032
#define DS_ASTASH 4096

typedef unsigned long long u64;

__device__ __forceinline__ u64 pack2f(float lo, float hi) {
    u64 r; asm("mov.b64 %0, {%1, %2};" : "=l"(r) : "f"(lo), "f"(hi)); return r;
}
__device__ __forceinline__ void unpack2f(u64 v, float& lo, float& hi) {
    asm("mov.b64 {%0, %1}, %2;" : "=f"(lo), "=f"(hi) : "l"(v));
}
__device__ __forceinline__ u64 ffma2(u64 a, u64 b, u64 c) {
    u64 d; asm("fma.rn.f32x2 %0, %1, %2, %3;" : "=l"(d) : "l"(a), "l"(b), "l"(c)); return d;
}
__device__ __forceinline__ u64 fmul2(u64 a, u64 b) {
    u64 d; asm("mul.rn.f32x2 %0, %1, %2;" : "=l"(d) : "l"(a), "l"(b)); return d;
}
__device__ __forceinline__ float ex2f(float x) {
    float r; asm("ex2.approx.ftz.f32 %0, %1;" : "=f"(r) : "f"(x)); return r;
}

// ---------------------------------------------------------------------------
// Single fused kernel. Per-block prep is cheap by construction:
//  - uniformity check = pure compares (no division)
//  - log2(w_k) = (alpha_k - m)*log2e - log2(sum)   (no per-row logf)
//  - __fdividef reciprocals, table written straight into shared
// Main loop = R8's SPT=3 scalar-LDS FFMA2 chains.
// ---------------------------------------------------------------------------
extern __shared__ float sB[];

__global__ void __launch_bounds__(128, 5)
gm_kernel(const float* __restrict__ sample,
          const float* __restrict__ alpha,
          const float* __restrict__ mu,
          const float* __restrict__ cov,
          float* __restrict__ out, int n_total) {
    __shared__ float red[128];
    __shared__ int sflag;

    const int tid = threadIdx.x;
    if (tid == 0) sflag = 1;

    // ---- softmax pieces over alpha (168 vals, 128 threads)
    const float a0v = alpha[tid];
    const float a1v = (tid < KCOMP - 128) ? alpha[tid + 128] : -1e30f;
    red[tid] = fmaxf(a0v, a1v); __syncthreads();
    for (int s = 64; s > 0; s >>= 1) { if (tid < s) red[tid] = fmaxf(red[tid], red[tid + s]); __syncthreads(); }
    const float mx = red[0]; __syncthreads();
    float ev = __expf(a0v - mx) + ((tid < KCOMP - 128) ? __expf(a1v - mx) : 0.f);
    red[tid] = ev; __syncthreads();
    for (int s = 64; s > 0; s >>= 1) { if (tid < s) red[tid] += red[tid + s]; __syncthreads(); }
    const float l2sum = log2f(red[0]);

    // ---- uniformity check: cov[k][d]*sc == cov[d]  (no divisions)
    {
        int ok = 1;
        for (int k = tid; k < KCOMP; k += 128) {
            const int i = k / MULT;
            #pragma unroll
            for (int d = 0; d < DIMS; d++) {
                float sc = (d < i) ? EPS_VAR : 1.0f;
                ok &= (cov[k * DIMS + d] * sc == cov[d]);
            }
        }
        if (!ok) atomicAnd(&sflag, 0);
    }
    __syncthreads();
    const int flag = sflag;

    // ---- build table in shared
    if (flag) {
        for (int k = tid; k < KCOMP; k += 128) {
            const int i = k / MULT;
            float sum_mu2inv = 0.f;
            #pragma unroll
            for (int d = 0; d < DIMS; d++) {
                float inv = __fdividef(1.0f, cov[d]);     // uniform across k
                float mm = mu[k * DIMS + d];
                sB[k * FROW + d] = LOG2E * inv * mm;
                sum_mu2inv += mm * mm * inv;
            }
            float log2det = (float)i * LOG2_EPSVAR + (float)(DIMS - i) * LOG2_BASECOV;
            float c = (alpha[k] - mx) * LOG2E - l2sum
                    - 0.5f * log2det - 0.5f * LOG2E * sum_mu2inv;
            sB[k * FROW + 20] = 0.f;
            sB[k * FROW + 21] = c;
            sB[k * FROW + 22] = 0.f;
            sB[k * FROW + 23] = 0.f;
        }
        if (tid < DIMS)
            sB[DS_AROW + tid] = -0.5f * LOG2E * __fdividef(1.0f, cov[tid]);
        if (tid >= DIMS && tid < 32) sB[DS_AROW + tid] = 0.f;
    } else {
        for (int k = tid; k < KCOMP; k += 128) {
            const int i = k / MULT;
            float sum_mu2inv = 0.f;
            #pragma unroll
            for (int d = 0; d < DIMS; d++) {
                float sc = (d < i) ? EPS_VAR : 1.0f;
                float inv = __fdividef(1.0f, cov[k * DIMS + d] * sc);
                float mm = mu[k * DIMS + d];
                sB[k * GROW + d]        = -0.5f * LOG2E * inv;
                sB[k * GROW + DIMS + d] =  LOG2E * inv * mm;
                sum_mu2inv += mm * mm * inv;
            }
            float log2det = (float)i * LOG2_EPSVAR + (float)(DIMS - i) * LOG2_BASECOV;
            sB[k * GROW + 2 * DIMS] = (alpha[k] - mx) * LOG2E - l2sum
                                    - 0.5f * log2det - 0.5f * LOG2E * sum_mu2inv
                                    + LOG2E * LOG_NORM;
            #pragma unroll
            for (int f = 2 * DIMS + 1; f < GROW; f++) sB[k * GROW + f] = 0.f;
        }
    }
    __syncthreads();

    // ---- load 3 samples' x as packed f32x2 pairs
    const int base = blockIdx.x * CHUNK;
    u64 x0[NPAIR], x1[NPAIR], x2[NPAIR];
    {
        const int n0 = base + tid, n1 = base + 128 + tid, n2 = base + 256 + tid;
        const size_t i0 = (n0 < n_total) ? (size_t)n0 : 0;
        const size_t i1 = (n1 < n_total) ? (size_t)n1 : 0;
        const size_t i2 = (n2 < n_total) ? (size_t)n2 : 0;
        const ulonglong2* p0 = (const ulonglong2*)(sample + i0 * DIMS);
        const ulonglong2* p1 = (const ulonglong2*)(sample + i1 * DIMS);
        const ulonglong2* p2 = (const ulonglong2*)(sample + i2 * DIMS);
        #pragma unroll
        for (int j = 0; j < 5; j++) {
            ulonglong2 q0 = p0[j], q1 = p1[j], q2 = p2[j];
            x0[2 * j] = q0.x; x0[2 * j + 1] = q0.y;
            x1[2 * j] = q1.x; x1[2 * j + 1] = q1.y;
            x2[2 * j] = q2.x; x2[2 * j + 1] = q2.y;
        }
    }

    float dens0 = 0.f, dens1 = 0.f, dens2 = 0.f;

    if (flag) {
        // ---- A_n = sum_d a_d * x_d^2, stashed in shared to free regs
        {
            const u64* ap = (const u64*)(sB + DS_AROW);
            u64 aA0 = fmul2(fmul2(x0[0], x0[0]), ap[0]);
            u64 aA1 = fmul2(fmul2(x1[0], x1[0]), ap[0]);
            u64 aA2 = fmul2(fmul2(x2[0], x2[0]), ap[0]);
            #pragma unroll
            for (int j = 1; j < NPAIR; j++) {
                aA0 = ffma2(fmul2(x0[j], x0[j]), ap[j], aA0);
                aA1 = ffma2(fmul2(x1[j], x1[j]), ap[j], aA1);
                aA2 = ffma2(fmul2(x2[j], x2[j]), ap[j], aA2);
            }
            float l, h;
            unpack2f(aA0, l, h); sB[DS_ASTASH + tid]       = l + h;
            unpack2f(aA1, l, h); sB[DS_ASTASH + 128 + tid] = l + h;
            unpack2f(aA2, l, h); sB[DS_ASTASH + 256 + tid] = l + h;
        }

        #pragma unroll 2
        for (int k = 0; k < KCOMP; k++) {
            const u64* R = (const u64*)(sB + k * FROW);   // g pairs [0..9], (0,c)[10]
            const u64 ck2 = R[10];
            u64 acc0 = ffma2(x0[0], R[0], ck2);
            u64 acc1 = ffma2(x1[0], R[0], ck2);
            u64 acc2 = ffma2(x2[0], R[0], ck2);
            #pragma unroll
            for (int j = 1; j < NPAIR; j++) {
                acc0 = ffma2(x0[j], R[j], acc0);
                acc1 = ffma2(x1[j], R[j], acc1);
                acc2 = ffma2(x2[j], R[j], acc2);
            }
            float l, h;
            unpack2f(acc0, l, h); dens0 += ex2f(l + h);
            unpack2f(acc1, l, h); dens1 += ex2f(l + h);
            unpack2f(acc2, l, h); dens2 += ex2f(l + h);
        }

        const int n0 = base + tid, n1 = base + 128 + tid, n2 = base + 256 + tid;
        if (n0 < n_total) out[n0] = fmaf(sB[DS_ASTASH + tid],       LN2F, logf(dens0)) + LOG_NORM;
        if (n1 < n_total) out[n1] = fmaf(sB[DS_ASTASH + 128 + tid], LN2F, logf(dens1)) + LOG_NORM;
        if (n2 < n_total) out[n2] = fmaf(sB[DS_ASTASH + 256 + tid], LN2F, logf(dens2)) + LOG_NORM;
    } else {
        // ---- general path: full Horner quadratic (c includes LOG2E*LOG_NORM)
        for (int k = 0; k < KCOMP; k++) {
            const u64* R = (const u64*)(sB + k * GROW);   // a[0..9], b[10..19], (c,0)[20]
            const u64 c2 = R[20];
            u64 acc0 = c2, acc1 = c2, acc2 = c2;
            #pragma unroll
            for (int j = 0; j < NPAIR; j++) {
                u64 t0 = ffma2(x0[j], R[j], R[10 + j]);
                acc0 = ffma2(x0[j], t0, acc0);
                u64 t1 = ffma2(x1[j], R[j], R[10 + j]);
                acc1 = ffma2(x1[j], t1, acc1);
                u64 t2 = ffma2(x2[j], R[j], R[10 + j]);
                acc2 = ffma2(x2[j], t2, acc2);
            }
            float l, h;
            unpack2f(acc0, l, h); dens0 += ex2f(l + h);
            unpack2f(acc1, l, h); dens1 += ex2f(l + h);
            unpack2f(acc2, l, h); dens2 += ex2f(l + h);
        }
        const int n0 = base + tid, n1 = base + 128 + tid, n2 = base + 256 + tid;
        if (n0 < n_total) out[n0] = logf(dens0);
        if (n1 < n_total) out[n1] = logf(dens1);
        if (n2 < n_total) out[n2] = logf(dens2);
    }
}

extern "C" void kernel_launch(void* const* d_in, const int* in_sizes, int n_in,
                              void* d_out, int out_size) {
    const float* sample = (const float*)d_in[0];
    const float* alpha  = (const float*)d_in[1];
    const float* mu     = (const float*)d_in[2];
    const float* cov    = (const float*)d_in[3];
    float* out = (float*)d_out;

    const int n_total = in_sizes[0] / DIMS;
    const int blocks = (n_total + CHUNK - 1) / CHUNK;

    static int attr_done = 0;
    if (!attr_done) {
        cudaFuncSetAttribute(gm_kernel, cudaFuncAttributeMaxDynamicSharedMemorySize,
                             DS_FLOATS * (int)sizeof(float));
        attr_done = 1;
    }
    gm_kernel<<<blocks, 128, DS_FLOATS * sizeof(float)>>>(sample, alpha, mu, cov, out, n_total);
}

// round 12
// speedup vs baseline: 1.2277x; 1.0677x over previous
#include <cuda_runtime.h>
#include <math.h>

#define DIMS 20
#define MULT 8
#define KCOMP 168
#define NPAIR (DIMS/2)
#define FROW 24              // fast row: g[20] | 0 | c | pad2   (96B)
#define GROW 48              // general row: a[20] | b[20] | c | pad
#define LOG_NORM (-18.378770664093453f)
#define LN2F 0.6931471805599453f
#define EPS_VAR 1.0f
#define BASE_COV 0.1f
#define LOG2E 1.4426950408889634f
#define LOG2_EPSVAR 0.0f
#define LOG2_BASECOV (-3.3219280948873623f)
#define SPT 3
#define CHUNK (128 * SPT)

typedef unsigned long long u64;

// staging written by prep kernel
__device__ float g_fast[4096];          // 168*24 rows, a-row at 4032, zero pad
__device__ float g_gen[KCOMP * GROW];
__device__ int   g_flag;

__device__ __forceinline__ u64 pack2f(float lo, float hi) {
    u64 r; asm("mov.b64 %0, {%1, %2};" : "=l"(r) : "f"(lo), "f"(hi)); return r;
}
__device__ __forceinline__ void unpack2f(u64 v, float& lo, float& hi) {
    asm("mov.b64 {%0, %1}, %2;" : "=f"(lo), "=f"(hi) : "l"(v));
}
__device__ __forceinline__ u64 ffma2(u64 a, u64 b, u64 c) {
    u64 d; asm("fma.rn.f32x2 %0, %1, %2, %3;" : "=l"(d) : "l"(a), "l"(b), "l"(c)); return d;
}
__device__ __forceinline__ u64 fmul2(u64 a, u64 b) {
    u64 d; asm("mul.rn.f32x2 %0, %1, %2;" : "=l"(d) : "l"(a), "l"(b)); return d;
}
__device__ __forceinline__ float ex2f(float x) {
    float r; asm("ex2.approx.ftz.f32 %0, %1;" : "=f"(r) : "f"(x)); return r;
}

// ---------------------------------------------------------------------------
// Prep kernel: ONE small launch, fast ops only. Flag first, then build only
// the layout that will be used.
// ---------------------------------------------------------------------------
__global__ void gm_prep_kernel(const float* __restrict__ alpha,
                               const float* __restrict__ mu,
                               const float* __restrict__ cov) {
    __shared__ float red[256];
    __shared__ int sflag;
    const int t = threadIdx.x;
    if (t == 0) sflag = 1;

    // softmax pieces
    float av = (t < KCOMP) ? alpha[t] : -1e30f;
    red[t] = av; __syncthreads();
    for (int s = 128; s > 0; s >>= 1) { if (t < s) red[t] = fmaxf(red[t], red[t + s]); __syncthreads(); }
    const float mx = red[0]; __syncthreads();
    float ev = (t < KCOMP) ? __expf(av - mx) : 0.f;
    red[t] = ev; __syncthreads();
    for (int s = 128; s > 0; s >>= 1) { if (t < s) red[t] += red[t + s]; __syncthreads(); }
    const float l2sum = log2f(red[0]);

    // uniformity flag (compares only)
    if (t < KCOMP) {
        const int i = t / MULT;
        int ok = 1;
        #pragma unroll
        for (int d = 0; d < DIMS; d++) {
            float sc = (d < i) ? EPS_VAR : 1.0f;
            ok &= (cov[t * DIMS + d] * sc == cov[d]);
        }
        if (!ok) atomicAnd(&sflag, 0);
    }
    __syncthreads();
    const int flag = sflag;

    if (t < KCOMP) {
        const int i = t / MULT;
        if (flag) {
            float sum_mu2inv = 0.f;
            #pragma unroll
            for (int d = 0; d < DIMS; d++) {
                float inv = __fdividef(1.0f, cov[d]);
                float mm = mu[t * DIMS + d];
                g_fast[t * FROW + d] = LOG2E * inv * mm;
                sum_mu2inv += mm * mm * inv;
            }
            float log2det = (float)i * LOG2_EPSVAR + (float)(DIMS - i) * LOG2_BASECOV;
            float c = (av - mx) * LOG2E - l2sum
                    - 0.5f * log2det - 0.5f * LOG2E * sum_mu2inv;
            g_fast[t * FROW + 20] = 0.f;
            g_fast[t * FROW + 21] = c;
            g_fast[t * FROW + 22] = 0.f;
            g_fast[t * FROW + 23] = 0.f;
            if (t < DIMS) g_fast[KCOMP * FROW + t] = -0.5f * LOG2E * __fdividef(1.0f, cov[t]);
            if (t >= DIMS && t < 64) g_fast[KCOMP * FROW + t] = 0.f;
        } else {
            float sum_mu2inv = 0.f;
            #pragma unroll
            for (int d = 0; d < DIMS; d++) {
                float sc = (d < i) ? EPS_VAR : 1.0f;
                float inv = __fdividef(1.0f, cov[t * DIMS + d] * sc);
                float mm = mu[t * DIMS + d];
                g_gen[t * GROW + d]        = -0.5f * LOG2E * inv;
                g_gen[t * GROW + DIMS + d] =  LOG2E * inv * mm;
                sum_mu2inv += mm * mm * inv;
            }
            float log2det = (float)i * LOG2_EPSVAR + (float)(DIMS - i) * LOG2_BASECOV;
            g_gen[t * GROW + 2 * DIMS] = (av - mx) * LOG2E - l2sum
                                       - 0.5f * log2det - 0.5f * LOG2E * sum_mu2inv
                                       + LOG2E * LOG_NORM;
            #pragma unroll
            for (int f = 2 * DIMS + 1; f < GROW; f++) g_gen[t * GROW + f] = 0.f;
        }
    }
    if (t == 0) g_flag = flag;
}

// ---------------------------------------------------------------------------
// Main kernel: 128 threads/block, SPT=3, scalar-LDS FFMA2 chains, A-term
// stashed in shared to keep regs <= 96 at occupancy 5.
// ---------------------------------------------------------------------------
__global__ void __launch_bounds__(128, 5)
gm_main_kernel(const float* __restrict__ sample, float* __restrict__ out, int n_total) {
    __shared__ float sB[8192];           // fast: rows[0,4032)+arow@4032; gen: rows[0,8064)
    __shared__ float sA[384];            // A-term stash
    const int tid = threadIdx.x;
    const int flag = g_flag;

    if (flag) {
        const float4* src = (const float4*)g_fast;
        float4* dst = (float4*)sB;
        #pragma unroll
        for (int it = 0; it < 8; it++) dst[tid + 128 * it] = src[tid + 128 * it];
    } else {
        const float4* src = (const float4*)g_gen;
        float4* dst = (float4*)sB;
        for (int idx = tid; idx < KCOMP * GROW / 4; idx += 128) dst[idx] = src[idx];
    }
    __syncthreads();

    const int base = blockIdx.x * CHUNK;
    u64 x0[NPAIR], x1[NPAIR], x2[NPAIR];
    {
        const int n0 = base + tid, n1 = base + 128 + tid, n2 = base + 256 + tid;
        const size_t i0 = (n0 < n_total) ? (size_t)n0 : 0;
        const size_t i1 = (n1 < n_total) ? (size_t)n1 : 0;
        const size_t i2 = (n2 < n_total) ? (size_t)n2 : 0;
        const ulonglong2* p0 = (const ulonglong2*)(sample + i0 * DIMS);
        const ulonglong2* p1 = (const ulonglong2*)(sample + i1 * DIMS);
        const ulonglong2* p2 = (const ulonglong2*)(sample + i2 * DIMS);
        #pragma unroll
        for (int j = 0; j < 5; j++) {
            ulonglong2 q0 = p0[j], q1 = p1[j], q2 = p2[j];
            x0[2 * j] = q0.x; x0[2 * j + 1] = q0.y;
            x1[2 * j] = q1.x; x1[2 * j + 1] = q1.y;
            x2[2 * j] = q2.x; x2[2 * j + 1] = q2.y;
        }
    }

    float dens0 = 0.f, dens1 = 0.f, dens2 = 0.f;

    if (flag) {
        // A_n = sum_d a_d x_d^2, stashed in shared to free registers
        {
            const u64* ap = (const u64*)(sB + KCOMP * FROW);
            u64 aA0 = fmul2(fmul2(x0[0], x0[0]), ap[0]);
            u64 aA1 = fmul2(fmul2(x1[0], x1[0]), ap[0]);
            u64 aA2 = fmul2(fmul2(x2[0], x2[0]), ap[0]);
            #pragma unroll
            for (int j = 1; j < NPAIR; j++) {
                aA0 = ffma2(fmul2(x0[j], x0[j]), ap[j], aA0);
                aA1 = ffma2(fmul2(x1[j], x1[j]), ap[j], aA1);
                aA2 = ffma2(fmul2(x2[j], x2[j]), ap[j], aA2);
            }
            float l, h;
            unpack2f(aA0, l, h); sA[tid]       = l + h;
            unpack2f(aA1, l, h); sA[128 + tid] = l + h;
            unpack2f(aA2, l, h); sA[256 + tid] = l + h;
        }

        #pragma unroll 2
        for (int k = 0; k < KCOMP; k++) {
            const u64* R = (const u64*)(sB + k * FROW);   // g pairs [0..9], (0,c)[10]
            const u64 ck2 = R[10];
            u64 acc0 = ffma2(x0[0], R[0], ck2);
            u64 acc1 = ffma2(x1[0], R[0], ck2);
            u64 acc2 = ffma2(x2[0], R[0], ck2);
            #pragma unroll
            for (int j = 1; j < NPAIR; j++) {
                acc0 = ffma2(x0[j], R[j], acc0);
                acc1 = ffma2(x1[j], R[j], acc1);
                acc2 = ffma2(x2[j], R[j], acc2);
            }
            float l, h;
            unpack2f(acc0, l, h); dens0 += ex2f(l + h);
            unpack2f(acc1, l, h); dens1 += ex2f(l + h);
            unpack2f(acc2, l, h); dens2 += ex2f(l + h);
        }

        const int n0 = base + tid, n1 = base + 128 + tid, n2 = base + 256 + tid;
        if (n0 < n_total) out[n0] = fmaf(sA[tid],       LN2F, __logf(dens0)) + LOG_NORM;
        if (n1 < n_total) out[n1] = fmaf(sA[128 + tid], LN2F, __logf(dens1)) + LOG_NORM;
        if (n2 < n_total) out[n2] = fmaf(sA[256 + tid], LN2F, __logf(dens2)) + LOG_NORM;
    } else {
        for (int k = 0; k < KCOMP; k++) {
            const u64* R = (const u64*)(sB + k * GROW);
            const u64 c2 = R[20];
            u64 acc0 = c2, acc1 = c2, acc2 = c2;
            #pragma unroll
            for (int j = 0; j < NPAIR; j++) {
                u64 t0 = ffma2(x0[j], R[j], R[10 + j]);
                acc0 = ffma2(x0[j], t0, acc0);
                u64 t1 = ffma2(x1[j], R[j], R[10 + j]);
                acc1 = ffma2(x1[j], t1, acc1);
                u64 t2 = ffma2(x2[j], R[j], R[10 + j]);
                acc2 = ffma2(x2[j], t2, acc2);
            }
            float l, h;
            unpack2f(acc0, l, h); dens0 += ex2f(l + h);
            unpack2f(acc1, l, h); dens1 += ex2f(l + h);
            unpack2f(acc2, l, h); dens2 += ex2f(l + h);
        }
        const int n0 = base + tid, n1 = base + 128 + tid, n2 = base + 256 + tid;
        if (n0 < n_total) out[n0] = __logf(dens0);
        if (n1 < n_total) out[n1] = __logf(dens1);
        if (n2 < n_total) out[n2] = __logf(dens2);
    }
}

extern "C" void kernel_launch(void* const* d_in, const int* in_sizes, int n_in,
                              void* d_out, int out_size) {
    const float* sample = (const float*)d_in[0];
    const float* alpha  = (const float*)d_in[1];
    const float* mu     = (const float*)d_in[2];
    const float* cov    = (const float*)d_in[3];
    float* out = (float*)d_out;

    const int n_total = in_sizes[0] / DIMS;
    const int blocks = (n_total + CHUNK - 1) / CHUNK;

    gm_prep_kernel<<<1, 256>>>(alpha, mu, cov);
    gm_main_kernel<<<blocks, 128>>>(sample, out, n_total);
}